// round 11
// baseline (speedup 1.0000x reference)
#include <cuda_runtime.h>
#include <math.h>

typedef unsigned long long ull;

// Problem constants
#define NROWS 131072
#define KSLOT 16
#define NBLK_A 148
#define NWARP_A (NBLK_A * 8)      // 1184

// -------- device scratch (static) --------
__device__ float g_qk[KSLOT * 256];     // qkg[s][f] = qk * gamma_f, scale folded
__device__ float g_qkb[KSLOT * 256];    // qk * beta_f
__device__ float g_qsum[KSLOT];         // sum_f qkg[s][f]
__device__ float g_c[KSLOT];            // sum_f qk*beta
__device__ float g_qT[256 * KSLOT];     // q transposed [d][s]
__device__ float g_part[NBLK_A * KSLOT * 256];   // per-block wx partials (2.4MB)
__device__ float g_rsA[NBLK_A * KSLOT];          // per-block A_s partials
__device__ float g_tA[NBLK_A * KSLOT];           // per-block t_s partials
__device__ float g_upd[KSLOT * 256];
__device__ float g_gi[768 * KSLOT];
__device__ float g_gh[768 * KSLOT];
__device__ float4 g_stats[NROWS / 2];   // per row-pair: (r0, r0*m0, r1, r1*m1)  (1MB)

// -------- f32x2 packed helpers --------
#define FMA2(d,a,b,c) asm("fma.rn.f32x2 %0, %1, %2, %3;" : "=l"(d) : "l"(a), "l"(b), "l"(c))
#define PACK2(d,lo,hi) asm("mov.b64 %0, {%1, %2};" : "=l"(d) : "r"(__float_as_uint(lo)), "r"(__float_as_uint(hi)))
#define UNPK2(lo,hi,src) do { unsigned _ul,_uh; \
    asm("mov.b64 {%0, %1}, %2;" : "=r"(_ul), "=r"(_uh) : "l"(src)); \
    lo = __uint_as_float(_ul); hi = __uint_as_float(_uh); } while(0)

// pass-A feature index owned by (i2, lane): pairs (F0, F0+1)
__device__ __forceinline__ int F0(int i2, int lane) {
    return (i2 >> 1) * 128 + 4 * lane + 2 * (i2 & 1);
}

// -------- warp helpers --------
// reduce-scatter 16 values across 32 lanes; returns sum for s=(lane>>1)&15
__device__ __forceinline__ float rs16(const float* v, int lane) {
    bool b4 = (lane & 16) != 0, b3 = (lane & 8) != 0, bb2 = (lane & 4) != 0, bb1 = (lane & 2) != 0;
    float w[8];
    #pragma unroll
    for (int i = 0; i < 8; i++) {
        float snd = b4 ? v[i] : v[i + 8];
        float kp  = b4 ? v[i + 8] : v[i];
        w[i] = kp + __shfl_xor_sync(0xffffffffu, snd, 16);
    }
    float u[4];
    #pragma unroll
    for (int i = 0; i < 4; i++) {
        float snd = b3 ? w[i] : w[i + 4];
        float kp  = b3 ? w[i + 4] : w[i];
        u[i] = kp + __shfl_xor_sync(0xffffffffu, snd, 8);
    }
    float x[2];
    #pragma unroll
    for (int i = 0; i < 2; i++) {
        float snd = bb2 ? u[i] : u[i + 2];
        float kp  = bb2 ? u[i + 2] : u[i];
        x[i] = kp + __shfl_xor_sync(0xffffffffu, snd, 4);
    }
    float snd = bb1 ? x[0] : x[1];
    float kp  = bb1 ? x[1] : x[0];
    float r = kp + __shfl_xor_sync(0xffffffffu, snd, 2);
    r += __shfl_xor_sync(0xffffffffu, r, 1);
    return r;
}

// reduce-scatter 16 values within each 16-lane HALF (4 levels).
// lane (h*16+q) returns sum over its half of v[q].
__device__ __forceinline__ float rs16h(const float* v, int lane) {
    bool b3 = (lane & 8) != 0, b2 = (lane & 4) != 0, b1 = (lane & 2) != 0, b0 = (lane & 1) != 0;
    float w[8];
    #pragma unroll
    for (int i = 0; i < 8; i++) {
        float snd = b3 ? v[i] : v[i + 8];
        float kp  = b3 ? v[i + 8] : v[i];
        w[i] = kp + __shfl_xor_sync(0xffffffffu, snd, 8);
    }
    float u[4];
    #pragma unroll
    for (int i = 0; i < 4; i++) {
        float snd = b2 ? w[i] : w[i + 4];
        float kp  = b2 ? w[i + 4] : w[i];
        u[i] = kp + __shfl_xor_sync(0xffffffffu, snd, 4);
    }
    float x[2];
    #pragma unroll
    for (int i = 0; i < 2; i++) {
        float snd = b1 ? u[i] : u[i + 2];
        float kp  = b1 ? u[i + 2] : u[i];
        x[i] = kp + __shfl_xor_sync(0xffffffffu, snd, 2);
    }
    float snd = b0 ? x[0] : x[1];
    float kp  = b0 ? x[1] : x[0];
    return kp + __shfl_xor_sync(0xffffffffu, snd, 1);
}

// block of 256 threads: mean + rstd of one 256-vector
__device__ __forceinline__ void block_stats256(float v, float* red, float& mean, float& rstd) {
    float s1 = v, s2 = v * v;
    #pragma unroll
    for (int o = 16; o; o >>= 1) {
        s1 += __shfl_xor_sync(0xffffffffu, s1, o);
        s2 += __shfl_xor_sync(0xffffffffu, s2, o);
    }
    int w = threadIdx.x >> 5;
    if ((threadIdx.x & 31) == 0) { red[w] = s1; red[8 + w] = s2; }
    __syncthreads();
    s1 = 0.f; s2 = 0.f;
    #pragma unroll
    for (int i = 0; i < 8; i++) { s1 += red[i]; s2 += red[8 + i]; }
    mean = s1 * (1.0f / 256.0f);
    float var = s2 * (1.0f / 256.0f) - mean * mean;
    rstd = rsqrtf(var + 1e-5f);
    __syncthreads();
}

// 512-thread block: stats over the 256 values held by threads t<256
__device__ __forceinline__ void stats256_512(float v, int t, float* red, float& mean, float& rstd) {
    bool act = t < 256;
    float s1 = act ? v : 0.f, s2 = act ? v * v : 0.f;
    #pragma unroll
    for (int o = 16; o; o >>= 1) {
        s1 += __shfl_xor_sync(0xffffffffu, s1, o);
        s2 += __shfl_xor_sync(0xffffffffu, s2, o);
    }
    int w = t >> 5;
    if ((t & 31) == 0) { red[w] = s1; red[16 + w] = s2; }
    __syncthreads();
    s1 = 0.f; s2 = 0.f;
    #pragma unroll
    for (int i = 0; i < 8; i++) { s1 += red[i]; s2 += red[16 + i]; }
    mean = s1 * (1.0f / 256.0f);
    float var = s2 * (1.0f / 256.0f) - mean * mean;
    rstd = rsqrtf(var + 1e-5f);
    __syncthreads();
}

// ================= k_prep: LN(slots_init) @ Wq -> g_qT =================
__global__ void k_prep(const float* __restrict__ slots_init,
                       const float* __restrict__ ln_s_g, const float* __restrict__ ln_s_b,
                       const float* __restrict__ Wq) {
    __shared__ float red[16];
    __shared__ float sv[256];
    int s = blockIdx.x, t = threadIdx.x;
    float v = slots_init[s * 256 + t];
    float mean, rstd;
    block_stats256(v, red, mean, rstd);
    sv[t] = (v - mean) * rstd * ln_s_g[t] + ln_s_b[t];
    __syncthreads();
    float a0 = 0.f, a1 = 0.f, a2 = 0.f, a3 = 0.f;
    #pragma unroll 4
    for (int d = 0; d < 256; d += 4) {
        a0 += sv[d] * Wq[d * 256 + t];
        a1 += sv[d + 1] * Wq[(d + 1) * 256 + t];
        a2 += sv[d + 2] * Wq[(d + 2) * 256 + t];
        a3 += sv[d + 3] * Wq[(d + 3) * 256 + t];
    }
    g_qT[t * 16 + s] = (a0 + a1) + (a2 + a3);
}

// ====== k_qk: qkg[s][f] = (q[s].Wk[f])/16 * gamma_f ; qkb = same * beta_f ======
__global__ void k_qk(const float* __restrict__ Wk,
                     const float* __restrict__ lnf_g, const float* __restrict__ lnf_b) {
    __shared__ float qT[4096];
    int t = threadIdx.x;
    for (int idx = t; idx < 4096; idx += 256) qT[idx] = g_qT[idx];
    __syncthreads();
    int lane = t & 31, w = t >> 5;
    int f = blockIdx.x * 8 + w;
    int c = lane >> 4, s = lane & 15;
    const float* wk = Wk + f * 256 + c;
    float a = 0.f;
    #pragma unroll 8
    for (int i = 0; i < 128; i++)
        a += qT[(2 * i + c) * 16 + s] * wk[2 * i];
    a += __shfl_xor_sync(0xffffffffu, a, 16);
    if (lane < 16) {
        float af = a * 0.0625f;       // scale = D^-0.5
        g_qk[lane * 256 + f]  = af * lnf_g[f];
        g_qkb[lane * 256 + f] = af * lnf_b[f];
    }
}

// ====== k_qfin: qsum[s] = sum_f qkg ; c[s] = sum_f qkb ======
__global__ void k_qfin() {
    int t = threadIdx.x;
    int w = t >> 5, lane = t & 31;
    float qs = 0.f, cc = 0.f;
    #pragma unroll
    for (int j = 0; j < 8; j++) {
        qs += g_qk[w * 256 + lane + 32 * j];
        cc += g_qkb[w * 256 + lane + 32 * j];
    }
    #pragma unroll
    for (int o = 16; o; o >>= 1) {
        qs += __shfl_xor_sync(0xffffffffu, qs, o);
        cc += __shfl_xor_sync(0xffffffffu, cc, o);
    }
    if (lane == 0) { g_qsum[w] = qs; g_c[w] = cc; }
}

// ================= pass A: raw-x logits + softmax + rank-16 accum =================
__global__ void __launch_bounds__(256, 1)
k_pass_a(const float* __restrict__ features) {
    extern __shared__ ull dyn[];
    ull* qk2 = dyn;                 // 2048 ull (16KB)
    ull* bufs = dyn + 2048;         // 4 * 2048 ull (64KB)
    __shared__ float rbuf[8][16], tbuf[8][16];

    int t = threadIdx.x;
    for (int idx = t; idx < 2048; idx += 256) {
        int s = idx >> 7, r = idx & 127, i2 = r >> 5, ln = r & 31;
        int f0 = F0(i2, ln);
        ull v; PACK2(v, g_qk[s * 256 + f0], g_qk[s * 256 + f0 + 1]);
        qk2[idx] = v;
    }
    __syncthreads();

    int lane = t & 31, w = t >> 5;
    int gw = blockIdx.x * 8 + w;
    int sl = (lane >> 1) & 15;
    float qs_l = g_qsum[sl];
    float c_l  = g_c[sl];
    ull ONE; PACK2(ONE, 1.0f, 1.0f);

    ull acc2[64];
    #pragma unroll
    for (int i = 0; i < 64; i++) acc2[i] = 0ull;
    float rsum = 0.f, tsum = 0.f;

    for (int pi = gw; pi < NROWS / 2; pi += NWARP_A) {
        const float4* fr = (const float4*)(features + (size_t)(2 * pi) * 256);
        float4 A0 = fr[lane], B0 = fr[32 + lane];
        float4 A1 = fr[64 + lane], B1 = fr[96 + lane];
        ull xv0[4] = { ((ull*)&A0)[0], ((ull*)&A0)[1], ((ull*)&B0)[0], ((ull*)&B0)[1] };
        ull xv1[4] = { ((ull*)&A1)[0], ((ull*)&A1)[1], ((ull*)&B1)[0], ((ull*)&B1)[1] };

        // stats on raw x (packed)
        ull sp0, sq0 = 0ull, sp1, sq1 = 0ull;
        FMA2(sp0, xv0[0], ONE, xv0[1]);
        { ull tmp; FMA2(tmp, xv0[2], ONE, xv0[3]); FMA2(sp0, tmp, ONE, sp0); }
        FMA2(sp1, xv1[0], ONE, xv1[1]);
        { ull tmp; FMA2(tmp, xv1[2], ONE, xv1[3]); FMA2(sp1, tmp, ONE, sp1); }
        #pragma unroll
        for (int i = 0; i < 4; i++) { FMA2(sq0, xv0[i], xv0[i], sq0); FMA2(sq1, xv1[i], xv1[i], sq1); }
        float lo, hi, s10, s20, s11, s21;
        UNPK2(lo, hi, sp0); s10 = lo + hi;
        UNPK2(lo, hi, sq0); s20 = lo + hi;
        UNPK2(lo, hi, sp1); s11 = lo + hi;
        UNPK2(lo, hi, sq1); s21 = lo + hi;

        // logits dot on raw x (independent of stats -> overlaps)
        float p0[16], p1[16];
        #pragma unroll
        for (int s = 0; s < 16; s++) {
            ull t0 = 0ull, t1 = 0ull;
            #pragma unroll
            for (int i2 = 0; i2 < 4; i2++) {
                ull q = qk2[(s * 4 + i2) * 32 + lane];
                FMA2(t0, q, xv0[i2], t0);
                FMA2(t1, q, xv1[i2], t1);
            }
            UNPK2(lo, hi, t0); p0[s] = lo + hi;
            UNPK2(lo, hi, t1); p1[s] = lo + hi;
        }

        #pragma unroll
        for (int o = 16; o; o >>= 1) {
            s10 += __shfl_xor_sync(0xffffffffu, s10, o);
            s20 += __shfl_xor_sync(0xffffffffu, s20, o);
            s11 += __shfl_xor_sync(0xffffffffu, s11, o);
            s21 += __shfl_xor_sync(0xffffffffu, s21, o);
        }
        float m0 = s10 * (1.f / 256), m1 = s11 * (1.f / 256);
        float r0 = rsqrtf(s20 * (1.f / 256) - m0 * m0 + 1e-5f);
        float r1 = rsqrtf(s21 * (1.f / 256) - m1 * m1 + 1e-5f);

        // store per-row stats for pass D: (r0, r0*m0, r1, r1*m1)
        if (lane == 0) g_stats[pi] = make_float4(r0, r0 * m0, r1, r1 * m1);

        float d0 = rs16(p0, lane);
        float d1 = rs16(p1, lane);
        // logit = rstd*dot - rstd*m*qsum + c (no max-subtract; |logit| bounded small)
        float e0 = __expf(fmaf(d0, r0, fmaf(-r0 * m0, qs_l, c_l)));
        float e1 = __expf(fmaf(d1, r1, fmaf(-r1 * m1, qs_l, c_l)));
        float den0 = e0, den1 = e1;
        #pragma unroll
        for (int o = 16; o; o >>= 1) {
            den0 += __shfl_xor_sync(0xffffffffu, den0, o);
            den1 += __shfl_xor_sync(0xffffffffu, den1, o);
        }
        float a0 = e0 * __fdividef(2.0f, den0);
        float a1 = e1 * __fdividef(2.0f, den1);
        float b0 = a0 * r0, b1 = a1 * r1;
        rsum += a0 + a1;
        tsum = fmaf(b0, m0, fmaf(b1, m1, tsum));

        #pragma unroll
        for (int s = 0; s < 16; s++) {
            float bv0 = __shfl_sync(0xffffffffu, b0, 2 * s);
            float bv1 = __shfl_sync(0xffffffffu, b1, 2 * s);
            ull B0p, B1p; PACK2(B0p, bv0, bv0); PACK2(B1p, bv1, bv1);
            #pragma unroll
            for (int i2 = 0; i2 < 4; i2++) {
                FMA2(acc2[s * 4 + i2], B0p, xv0[i2], acc2[s * 4 + i2]);
                FMA2(acc2[s * 4 + i2], B1p, xv1[i2], acc2[s * 4 + i2]);
            }
        }
    }

    // ---- block-level tree reduction of acc2 (8 warps -> 1) ----
    if (!(lane & 1)) { rbuf[w][lane >> 1] = rsum; tbuf[w][lane >> 1] = tsum; }
    __syncthreads();
    if (w >= 4) {
        #pragma unroll
        for (int i = 0; i < 64; i++) bufs[(w - 4) * 2048 + i * 32 + lane] = acc2[i];
    }
    __syncthreads();
    if (w < 4) {
        #pragma unroll
        for (int i = 0; i < 64; i++) {
            ull v = bufs[w * 2048 + i * 32 + lane];
            FMA2(acc2[i], v, ONE, acc2[i]);
        }
    }
    __syncthreads();
    if (w == 2 || w == 3) {
        #pragma unroll
        for (int i = 0; i < 64; i++) bufs[w * 2048 + i * 32 + lane] = acc2[i];
    }
    __syncthreads();
    if (w < 2) {
        #pragma unroll
        for (int i = 0; i < 64; i++) {
            ull v = bufs[(w + 2) * 2048 + i * 32 + lane];
            FMA2(acc2[i], v, ONE, acc2[i]);
        }
    }
    __syncthreads();
    if (w == 1) {
        #pragma unroll
        for (int i = 0; i < 64; i++) bufs[2048 + i * 32 + lane] = acc2[i];
    }
    __syncthreads();
    if (w == 0) {
        float* gp = g_part + (size_t)blockIdx.x * 4096;
        #pragma unroll
        for (int s = 0; s < 16; s++) {
            #pragma unroll
            for (int i2 = 0; i2 < 4; i2++) {
                ull v = bufs[2048 + (s * 4 + i2) * 32 + lane];
                FMA2(acc2[s * 4 + i2], v, ONE, acc2[s * 4 + i2]);
                *(ull*)(gp + s * 256 + F0(i2, lane)) = acc2[s * 4 + i2];
            }
        }
        if (lane < 16) {
            float r = 0.f, tt = 0.f;
            #pragma unroll
            for (int ww = 0; ww < 8; ww++) { r += rbuf[ww][lane]; tt += tbuf[ww][lane]; }
            g_rsA[blockIdx.x * 16 + lane] = r;
            g_tA[blockIdx.x * 16 + lane] = tt;
        }
    }
}

// ====== k_upd: reduce partials, reconstruct LN-affine, Wv GEMV ======
__global__ void k_upd(const float* __restrict__ Wv,
                      const float* __restrict__ lnf_g, const float* __restrict__ lnf_b) {
    __shared__ float red[16];
    __shared__ float shv[256];
    int s = blockIdx.x, t = threadIdx.x;
    int lane = t & 31, wid = t >> 5;

    float av = (t < NBLK_A) ? g_rsA[t * 16 + s] : 0.f;
    float tv = (t < NBLK_A) ? g_tA[t * 16 + s] : 0.f;
    #pragma unroll
    for (int o = 16; o; o >>= 1) {
        av += __shfl_xor_sync(0xffffffffu, av, o);
        tv += __shfl_xor_sync(0xffffffffu, tv, o);
    }
    if (lane == 0) { red[wid] = av; red[8 + wid] = tv; }
    __syncthreads();
    float A = 0.f, T = 0.f;
    #pragma unroll
    for (int i = 0; i < 8; i++) { A += red[i]; T += red[8 + i]; }

    // 148 = 37*4: 4 independent accumulators
    const float* gp = g_part + s * 256 + t;
    float wx0 = 0.f, wx1 = 0.f, wx2 = 0.f, wx3 = 0.f;
    for (int b = 0; b < NBLK_A; b += 4) {
        wx0 += gp[(size_t)b * 4096];
        wx1 += gp[(size_t)(b + 1) * 4096];
        wx2 += gp[(size_t)(b + 2) * 4096];
        wx3 += gp[(size_t)(b + 3) * 4096];
    }
    float wx = (wx0 + wx1) + (wx2 + wx3);

    float wfeat = lnf_g[t] * (wx - T) + lnf_b[t] * A;
    shv[t] = wfeat;
    __syncthreads();

    float inv = 1.0f / (A + 1.0f);   // EPSILON = 1.0
    float a0 = 0.f, a1 = 0.f, a2 = 0.f, a3 = 0.f;
    #pragma unroll 4
    for (int f = 0; f < 256; f += 4) {
        a0 += shv[f] * Wv[f * 256 + t];
        a1 += shv[f + 1] * Wv[(f + 1) * 256 + t];
        a2 += shv[f + 2] * Wv[(f + 2) * 256 + t];
        a3 += shv[f + 3] * Wv[(f + 3) * 256 + t];
    }
    g_upd[s * 256 + t] = ((a0 + a1) + (a2 + a3)) * inv;
}

// ================= k_gates: GRU gi/gh, warp per output j =================
__global__ void k_gates(const float* __restrict__ wih, const float* __restrict__ whh,
                        const float* __restrict__ slots_init) {
    __shared__ float upd_t[4096];
    __shared__ float h_t[4096];
    int t = threadIdx.x;
    for (int idx = t; idx < 4096; idx += 256) {
        int s = idx >> 8, d = idx & 255;
        upd_t[d * 16 + s] = g_upd[idx];
        h_t[d * 16 + s] = slots_init[idx];
    }
    __syncthreads();
    int lane = t & 31, w = t >> 5;
    int j = blockIdx.x * 8 + w;
    int c = lane >> 4, s = lane & 15;
    const float* wi = wih + (size_t)j * 256 + c;
    const float* wh = whh + (size_t)j * 256 + c;
    float ai = 0.f, ah = 0.f;
    #pragma unroll 8
    for (int i = 0; i < 128; i++) {
        int d = 2 * i + c;
        ai += upd_t[d * 16 + s] * wi[2 * i];
        ah += h_t[d * 16 + s] * wh[2 * i];
    }
    ai += __shfl_xor_sync(0xffffffffu, ai, 16);
    ah += __shfl_xor_sync(0xffffffffu, ah, 16);
    if (lane < 16) {
        g_gi[j * 16 + lane] = ai;
        g_gh[j * 16 + lane] = ah;
    }
}

// ====== k_tail: GRU pointwise + LN_m + MLP(residual) + out_slots + LN_s + qproj ======
__global__ void __launch_bounds__(512)
k_tail(const float* __restrict__ slots_init,
       const float* __restrict__ bih, const float* __restrict__ bhh,
       const float* __restrict__ lnm_g, const float* __restrict__ lnm_b,
       const float* __restrict__ w1, const float* __restrict__ b1,
       const float* __restrict__ w2, const float* __restrict__ b2p,
       const float* __restrict__ lns_g, const float* __restrict__ lns_b,
       const float* __restrict__ Wq, float* __restrict__ out_slots) {
    __shared__ float red[32];
    __shared__ float hl[256];
    __shared__ float hid[512];
    __shared__ float sv[256];
    int s = blockIdx.x, t = threadIdx.x;

    float hnew = 0.f;
    if (t < 256) {
        float gi0 = g_gi[t * 16 + s] + bih[t];
        float gi1 = g_gi[(256 + t) * 16 + s] + bih[256 + t];
        float gi2 = g_gi[(512 + t) * 16 + s] + bih[512 + t];
        float gh0 = g_gh[t * 16 + s] + bhh[t];
        float gh1 = g_gh[(256 + t) * 16 + s] + bhh[256 + t];
        float gh2 = g_gh[(512 + t) * 16 + s] + bhh[512 + t];
        float h = slots_init[s * 256 + t];
        float r = 1.0f / (1.0f + __expf(-(gi0 + gh0)));
        float z = 1.0f / (1.0f + __expf(-(gi1 + gh1)));
        float nn = tanhf(gi2 + r * gh2);
        hnew = (1.0f - z) * nn + z * h;
    }
    float mean, rstd;
    stats256_512(hnew, t, red, mean, rstd);
    if (t < 256) hl[t] = (hnew - mean) * rstd * lnm_g[t] + lnm_b[t];
    __syncthreads();

    // mlp1: all 512 threads, one output each
    float a0 = b1[t], a1 = 0.f, a2 = 0.f, a3 = 0.f;
    #pragma unroll 4
    for (int d = 0; d < 256; d += 4) {
        a0 += hl[d] * w1[d * 512 + t];
        a1 += hl[d + 1] * w1[(d + 1) * 512 + t];
        a2 += hl[d + 2] * w1[(d + 2) * 512 + t];
        a3 += hl[d + 3] * w1[(d + 3) * 512 + t];
    }
    hid[t] = fmaxf((a0 + a1) + (a2 + a3), 0.f);
    __syncthreads();

    // mlp2 + residual: t<256
    float sf = 0.f;
    if (t < 256) {
        float o0 = b2p[t], o1 = 0.f, o2 = 0.f, o3 = 0.f;
        #pragma unroll 4
        for (int r = 0; r < 512; r += 4) {
            o0 += hid[r] * w2[r * 256 + t];
            o1 += hid[r + 1] * w2[(r + 1) * 256 + t];
            o2 += hid[r + 2] * w2[(r + 2) * 256 + t];
            o3 += hid[r + 3] * w2[(r + 3) * 256 + t];
        }
        sf = hnew + ((o0 + o1) + (o2 + o3));
        out_slots[s * 256 + t] = sf;
    }
    stats256_512(sf, t, red, mean, rstd);
    if (t < 256) sv[t] = (sf - mean) * rstd * lns_g[t] + lns_b[t];
    __syncthreads();

    if (t < 256) {
        float q0 = 0.f, q1 = 0.f, q2 = 0.f, q3 = 0.f;
        #pragma unroll 4
        for (int d = 0; d < 256; d += 4) {
            q0 += sv[d] * Wq[d * 256 + t];
            q1 += sv[d + 1] * Wq[(d + 1) * 256 + t];
            q2 += sv[d + 2] * Wq[(d + 2) * 256 + t];
            q3 += sv[d + 3] * Wq[(d + 3) * 256 + t];
        }
        g_qT[t * 16 + s] = (q0 + q1) + (q2 + q3);
    }
}

// ========== pass D: quad layout (half-warp rows), precomputed stats, free regs ==========
// lane = (h, q): half h owns rows {4pi+h, 4pi+2+h}; lane q owns features f = 4q+64c(+0..3).
// qk LDS.64 are 16-address broadcasts (1 crossbar cycle) shared by 2 rows: 32 cyc/row.
__global__ void __launch_bounds__(256)
k_pass_d(const float* __restrict__ features, float* __restrict__ out_attn) {
    __shared__ ull qk2s[2048];   // [(s*8+j)*16 + q] = pack(qk[s][4q+64(j>>1)+2(j&1)], +1)
    int t = threadIdx.x;
    for (int idx = t; idx < 2048; idx += 256) {
        int s = idx >> 7, r = idx & 127, j = r >> 4, q = r & 15;
        int f = 4 * q + 64 * (j >> 1) + 2 * (j & 1);
        ull v; PACK2(v, g_qk[s * 256 + f], g_qk[s * 256 + f + 1]);
        qk2s[idx] = v;
    }
    __syncthreads();

    int lane = t & 31, w = t >> 5;
    int q = lane & 15, h = lane >> 4;
    int gw = blockIdx.x * 8 + w;
    int nw = gridDim.x * 8;
    float qs_l = g_qsum[q];
    float c_l  = g_c[q];

    for (int pi = gw; pi < NROWS / 4; pi += nw) {
        const float4* Fa = (const float4*)features + (size_t)(4 * pi + h) * 64;
        const float4* Fb = Fa + 128;   // rows +2
        float4 va0 = Fa[q], va1 = Fa[q + 16], va2 = Fa[q + 32], va3 = Fa[q + 48];
        float4 vb0 = Fb[q], vb1 = Fb[q + 16], vb2 = Fb[q + 32], vb3 = Fb[q + 48];
        ull xa[8] = { ((ull*)&va0)[0], ((ull*)&va0)[1], ((ull*)&va1)[0], ((ull*)&va1)[1],
                      ((ull*)&va2)[0], ((ull*)&va2)[1], ((ull*)&va3)[0], ((ull*)&va3)[1] };
        ull xb[8] = { ((ull*)&vb0)[0], ((ull*)&vb0)[1], ((ull*)&vb1)[0], ((ull*)&vb1)[1],
                      ((ull*)&vb2)[0], ((ull*)&vb2)[1], ((ull*)&vb3)[0], ((ull*)&vb3)[1] };

        // precomputed stats: g_stats[2pi]=(r,rm for rows 4pi,4pi+1), [2pi+1]=(rows 4pi+2,4pi+3)
        float4 sA = g_stats[2 * pi];
        float4 sB = g_stats[2 * pi + 1];
        float ra  = h ? sA.z : sA.x;
        float rma = h ? sA.w : sA.y;
        float rb  = h ? sB.z : sB.x;
        float rmb = h ? sB.w : sB.y;

        // logits partials (broadcast qk LDS shared by both row-sets)
        float pa[16], pb[16];
        #pragma unroll
        for (int s = 0; s < 16; s++) {
            ull t0 = 0ull, t1 = 0ull;
            #pragma unroll
            for (int j = 0; j < 8; j++) {
                ull qv = qk2s[(s * 8 + j) * 16 + q];
                FMA2(t0, qv, xa[j], t0);
                FMA2(t1, qv, xb[j], t1);
            }
            float lo, hi;
            UNPK2(lo, hi, t0); pa[s] = lo + hi;
            UNPK2(lo, hi, t1); pb[s] = lo + hi;
        }

        float da = rs16h(pa, lane);
        float db = rs16h(pb, lane);
        float ea = __expf(fmaf(da, ra, fmaf(-rma, qs_l, c_l)));
        float eb = __expf(fmaf(db, rb, fmaf(-rmb, qs_l, c_l)));
        float dena = ea, denb = eb;
        #pragma unroll
        for (int o = 1; o < 16; o <<= 1) {
            dena += __shfl_xor_sync(0xffffffffu, dena, o);
            denb += __shfl_xor_sync(0xffffffffu, denb, o);
        }
        float aa = ea * __fdividef(1.0f, dena);
        float ab = eb * __fdividef(1.0f, denb);

        // rows {4pi, 4pi+1} and {4pi+2, 4pi+3}: warp's 2 stores are each one 128B line
        out_attn[(size_t)(4 * pi + h) * 16 + q] = aa;
        out_attn[(size_t)(4 * pi + 2 + h) * 16 + q] = ab;
    }
}

// ================= launcher =================
extern "C" void kernel_launch(void* const* d_in, const int* in_sizes, int n_in,
                              void* d_out, int out_size) {
    const float* features   = (const float*)d_in[0];
    const float* ln_f_g     = (const float*)d_in[1];
    const float* ln_f_b     = (const float*)d_in[2];
    const float* ln_s_g     = (const float*)d_in[3];
    const float* ln_s_b     = (const float*)d_in[4];
    const float* ln_m_g     = (const float*)d_in[5];
    const float* ln_m_b     = (const float*)d_in[6];
    const float* Wq         = (const float*)d_in[7];
    const float* Wk         = (const float*)d_in[8];
    const float* Wv         = (const float*)d_in[9];
    const float* gru_wih    = (const float*)d_in[10];
    const float* gru_whh    = (const float*)d_in[11];
    const float* gru_bih    = (const float*)d_in[12];
    const float* gru_bhh    = (const float*)d_in[13];
    const float* mlp_w1     = (const float*)d_in[14];
    const float* mlp_b1     = (const float*)d_in[15];
    const float* mlp_w2     = (const float*)d_in[16];
    const float* mlp_b2     = (const float*)d_in[17];
    const float* slots_init = (const float*)d_in[18];
    // d_in[19] = num_iter (fixed at 2 -> exactly one update iteration)

    float* out = (float*)d_out;   // [0:4096) slots, [4096:) attn [N,16]

    const int DYN_A = 5 * 2048 * sizeof(ull);  // 80KB
    cudaFuncSetAttribute(k_pass_a, cudaFuncAttributeMaxDynamicSharedMemorySize, DYN_A);

    k_prep<<<KSLOT, 256>>>(slots_init, ln_s_g, ln_s_b, Wq);
    k_qk<<<32, 256>>>(Wk, ln_f_g, ln_f_b);
    k_qfin<<<1, 512>>>();
    k_pass_a<<<NBLK_A, 256, DYN_A>>>(features);
    k_upd<<<KSLOT, 256>>>(Wv, ln_f_g, ln_f_b);
    k_gates<<<96, 256>>>(gru_wih, gru_whh, slots_init);
    k_tail<<<KSLOT, 512>>>(slots_init, gru_bih, gru_bhh, ln_m_g, ln_m_b,
                           mlp_w1, mlp_b1, mlp_w2, mlp_b2,
                           ln_s_g, ln_s_b, Wq, out);
    k_qk<<<32, 256>>>(Wk, ln_f_g, ln_f_b);
    k_qfin<<<1, 512>>>();
    k_pass_d<<<592, 256>>>(features, out + KSLOT * 256);
}

// round 12
// speedup vs baseline: 1.1783x; 1.1783x over previous
#include <cuda_runtime.h>
#include <math.h>

typedef unsigned long long ull;

// Problem constants
#define NROWS 131072
#define KSLOT 16
#define NBLK_A 148
#define NWARP_A (NBLK_A * 8)      // 1184

// -------- device scratch (static) --------
__device__ float g_qk[KSLOT * 256];     // qkg[s][f] = qk * gamma_f, scale folded
__device__ float g_qkb[KSLOT * 256];    // qk * beta_f
__device__ float g_qsum[KSLOT];         // sum_f qkg[s][f]
__device__ float g_c[KSLOT];            // sum_f qk*beta
__device__ float g_qT[256 * KSLOT];     // q transposed [d][s]
__device__ float g_part[NBLK_A * KSLOT * 256];   // per-block wx partials (2.4MB)
__device__ float g_rsA[NBLK_A * KSLOT];          // per-block A_s partials
__device__ float g_tA[NBLK_A * KSLOT];           // per-block t_s partials
__device__ float g_upd[KSLOT * 256];
__device__ float g_gi[768 * KSLOT];
__device__ float g_gh[768 * KSLOT];
__device__ float g_hnew[KSLOT * 256];
__device__ float g_hln[KSLOT * 256];
__device__ float g_hid[KSLOT * 512];
__device__ float g_sink[256];           // prefetch sink (not an output)

// -------- f32x2 packed helpers --------
#define FMA2(d,a,b,c) asm("fma.rn.f32x2 %0, %1, %2, %3;" : "=l"(d) : "l"(a), "l"(b), "l"(c))
#define PACK2(d,lo,hi) asm("mov.b64 %0, {%1, %2};" : "=l"(d) : "r"(__float_as_uint(lo)), "r"(__float_as_uint(hi)))
#define UNPK2(lo,hi,src) do { unsigned _ul,_uh; \
    asm("mov.b64 {%0, %1}, %2;" : "=r"(_ul), "=r"(_uh) : "l"(src)); \
    lo = __uint_as_float(_ul); hi = __uint_as_float(_uh); } while(0)

// feature index owned by (i2, lane): pairs (F0, F0+1)
__device__ __forceinline__ int F0(int i2, int lane) {
    return (i2 >> 1) * 128 + 4 * lane + 2 * (i2 & 1);
}

// -------- warp helpers --------
// reduce-scatter 16 values across 32 lanes; returns sum for s=(lane>>1)&15
__device__ __forceinline__ float rs16(const float* v, int lane) {
    bool b4 = (lane & 16) != 0, b3 = (lane & 8) != 0, bb2 = (lane & 4) != 0, bb1 = (lane & 2) != 0;
    float w[8];
    #pragma unroll
    for (int i = 0; i < 8; i++) {
        float snd = b4 ? v[i] : v[i + 8];
        float kp  = b4 ? v[i + 8] : v[i];
        w[i] = kp + __shfl_xor_sync(0xffffffffu, snd, 16);
    }
    float u[4];
    #pragma unroll
    for (int i = 0; i < 4; i++) {
        float snd = b3 ? w[i] : w[i + 4];
        float kp  = b3 ? w[i + 4] : w[i];
        u[i] = kp + __shfl_xor_sync(0xffffffffu, snd, 8);
    }
    float x[2];
    #pragma unroll
    for (int i = 0; i < 2; i++) {
        float snd = bb2 ? u[i] : u[i + 2];
        float kp  = bb2 ? u[i + 2] : u[i];
        x[i] = kp + __shfl_xor_sync(0xffffffffu, snd, 4);
    }
    float snd = bb1 ? x[0] : x[1];
    float kp  = bb1 ? x[1] : x[0];
    float r = kp + __shfl_xor_sync(0xffffffffu, snd, 2);
    r += __shfl_xor_sync(0xffffffffu, r, 1);
    return r;
}

// block of 256 threads: mean + rstd of one 256-vector
__device__ __forceinline__ void block_stats256(float v, float* red, float& mean, float& rstd) {
    float s1 = v, s2 = v * v;
    #pragma unroll
    for (int o = 16; o; o >>= 1) {
        s1 += __shfl_xor_sync(0xffffffffu, s1, o);
        s2 += __shfl_xor_sync(0xffffffffu, s2, o);
    }
    int w = threadIdx.x >> 5;
    if ((threadIdx.x & 31) == 0) { red[w] = s1; red[8 + w] = s2; }
    __syncthreads();
    s1 = 0.f; s2 = 0.f;
    #pragma unroll
    for (int i = 0; i < 8; i++) { s1 += red[i]; s2 += red[8 + i]; }
    mean = s1 * (1.0f / 256.0f);
    float var = s2 * (1.0f / 256.0f) - mean * mean;
    rstd = rsqrtf(var + 1e-5f);
    __syncthreads();
}

// ================= k_pref: warm L2 with weight tensors (sum -> sink) ==============
__global__ void k_pref(const float4* __restrict__ p0, int n0,
                       const float4* __restrict__ p1, int n1,
                       const float4* __restrict__ p2, int n2,
                       const float4* __restrict__ p3, int n3,
                       const float4* __restrict__ p4, int n4,
                       const float4* __restrict__ p5, int n5,
                       const float4* __restrict__ p6, int n6) {
    int stride = gridDim.x * blockDim.x;
    int i0 = blockIdx.x * blockDim.x + threadIdx.x;
    float s = 0.f;
    for (int i = i0; i < n0; i += stride) { float4 v = p0[i]; s += (v.x + v.y) + (v.z + v.w); }
    for (int i = i0; i < n1; i += stride) { float4 v = p1[i]; s += (v.x + v.y) + (v.z + v.w); }
    for (int i = i0; i < n2; i += stride) { float4 v = p2[i]; s += (v.x + v.y) + (v.z + v.w); }
    for (int i = i0; i < n3; i += stride) { float4 v = p3[i]; s += (v.x + v.y) + (v.z + v.w); }
    for (int i = i0; i < n4; i += stride) { float4 v = p4[i]; s += (v.x + v.y) + (v.z + v.w); }
    for (int i = i0; i < n5; i += stride) { float4 v = p5[i]; s += (v.x + v.y) + (v.z + v.w); }
    for (int i = i0; i < n6; i += stride) { float4 v = p6[i]; s += (v.x + v.y) + (v.z + v.w); }
    g_sink[i0 & 255] = s;   // scratch sink (not program output)
}

// ================= k_prep: LN(slots_init) @ Wq -> g_qT =================
__global__ void k_prep(const float* __restrict__ slots_init,
                       const float* __restrict__ ln_s_g, const float* __restrict__ ln_s_b,
                       const float* __restrict__ Wq) {
    __shared__ float red[16];
    __shared__ float sv[256];
    int s = blockIdx.x, t = threadIdx.x;
    float v = slots_init[s * 256 + t];
    float mean, rstd;
    block_stats256(v, red, mean, rstd);
    sv[t] = (v - mean) * rstd * ln_s_g[t] + ln_s_b[t];
    __syncthreads();
    float a0 = 0.f, a1 = 0.f, a2 = 0.f, a3 = 0.f;
    #pragma unroll 4
    for (int d = 0; d < 256; d += 4) {
        a0 += sv[d] * Wq[d * 256 + t];
        a1 += sv[d + 1] * Wq[(d + 1) * 256 + t];
        a2 += sv[d + 2] * Wq[(d + 2) * 256 + t];
        a3 += sv[d + 3] * Wq[(d + 3) * 256 + t];
    }
    g_qT[t * 16 + s] = (a0 + a1) + (a2 + a3);
}

// ====== k_qk (smem-staged): qkg[s][f] = (q[s].Wk[f])/16 * gamma_f ; qkb likewise ======
// 16 blocks; block b covers f in [16b, 16b+16). Wk rows staged coalesced into smem.
__global__ void k_qk(const float* __restrict__ Wk,
                     const float* __restrict__ lnf_g, const float* __restrict__ lnf_b) {
    __shared__ float qT[4096];
    __shared__ float wk_sh[4096];
    int t = threadIdx.x, b = blockIdx.x;
    for (int idx = t; idx < 4096; idx += 256) {
        qT[idx] = g_qT[idx];
        wk_sh[idx] = Wk[b * 4096 + idx];   // rows 16b..16b+15, contiguous
    }
    __syncthreads();
    int fi = t >> 4, s = t & 15;
    int f = b * 16 + fi;
    const float* wr = wk_sh + fi * 256;
    float a0 = 0.f, a1 = 0.f, a2 = 0.f, a3 = 0.f;
    #pragma unroll 4
    for (int d = 0; d < 256; d += 4) {
        a0 += qT[d * 16 + s] * wr[d];
        a1 += qT[(d + 1) * 16 + s] * wr[d + 1];
        a2 += qT[(d + 2) * 16 + s] * wr[d + 2];
        a3 += qT[(d + 3) * 16 + s] * wr[d + 3];
    }
    float af = ((a0 + a1) + (a2 + a3)) * 0.0625f;   // scale = D^-0.5
    g_qk[s * 256 + f]  = af * lnf_g[f];
    g_qkb[s * 256 + f] = af * lnf_b[f];
}

// ====== k_qfin: qsum[s] = sum_f qkg ; c[s] = sum_f qkb ======
__global__ void k_qfin() {
    int t = threadIdx.x;
    int w = t >> 5, lane = t & 31;
    float qs = 0.f, cc = 0.f;
    #pragma unroll
    for (int j = 0; j < 8; j++) {
        qs += g_qk[w * 256 + lane + 32 * j];
        cc += g_qkb[w * 256 + lane + 32 * j];
    }
    #pragma unroll
    for (int o = 16; o; o >>= 1) {
        qs += __shfl_xor_sync(0xffffffffu, qs, o);
        cc += __shfl_xor_sync(0xffffffffu, cc, o);
    }
    if (lane == 0) { g_qsum[w] = qs; g_c[w] = cc; }
}

// ================= pass A: raw-x logits + softmax + rank-16 accum =================
__global__ void __launch_bounds__(256, 1)
k_pass_a(const float* __restrict__ features) {
    extern __shared__ ull dyn[];
    ull* qk2 = dyn;                 // 2048 ull (16KB)
    ull* bufs = dyn + 2048;         // 4 * 2048 ull (64KB)
    __shared__ float rbuf[8][16], tbuf[8][16];

    int t = threadIdx.x;
    for (int idx = t; idx < 2048; idx += 256) {
        int s = idx >> 7, r = idx & 127, i2 = r >> 5, ln = r & 31;
        int f0 = F0(i2, ln);
        ull v; PACK2(v, g_qk[s * 256 + f0], g_qk[s * 256 + f0 + 1]);
        qk2[idx] = v;
    }
    __syncthreads();

    int lane = t & 31, w = t >> 5;
    int gw = blockIdx.x * 8 + w;
    int sl = (lane >> 1) & 15;
    float qs_l = g_qsum[sl];
    float c_l  = g_c[sl];
    ull ONE; PACK2(ONE, 1.0f, 1.0f);

    ull acc2[64];
    #pragma unroll
    for (int i = 0; i < 64; i++) acc2[i] = 0ull;
    float rsum = 0.f, tsum = 0.f;

    for (int pi = gw; pi < NROWS / 2; pi += NWARP_A) {
        const float4* fr = (const float4*)(features + (size_t)(2 * pi) * 256);
        float4 A0 = fr[lane], B0 = fr[32 + lane];
        float4 A1 = fr[64 + lane], B1 = fr[96 + lane];
        ull xv0[4] = { ((ull*)&A0)[0], ((ull*)&A0)[1], ((ull*)&B0)[0], ((ull*)&B0)[1] };
        ull xv1[4] = { ((ull*)&A1)[0], ((ull*)&A1)[1], ((ull*)&B1)[0], ((ull*)&B1)[1] };

        // stats on raw x (packed)
        ull sp0, sq0 = 0ull, sp1, sq1 = 0ull;
        FMA2(sp0, xv0[0], ONE, xv0[1]);
        { ull tmp; FMA2(tmp, xv0[2], ONE, xv0[3]); FMA2(sp0, tmp, ONE, sp0); }
        FMA2(sp1, xv1[0], ONE, xv1[1]);
        { ull tmp; FMA2(tmp, xv1[2], ONE, xv1[3]); FMA2(sp1, tmp, ONE, sp1); }
        #pragma unroll
        for (int i = 0; i < 4; i++) { FMA2(sq0, xv0[i], xv0[i], sq0); FMA2(sq1, xv1[i], xv1[i], sq1); }
        float lo, hi, s10, s20, s11, s21;
        UNPK2(lo, hi, sp0); s10 = lo + hi;
        UNPK2(lo, hi, sq0); s20 = lo + hi;
        UNPK2(lo, hi, sp1); s11 = lo + hi;
        UNPK2(lo, hi, sq1); s21 = lo + hi;

        // logits dot on raw x (independent of stats -> overlaps)
        float p0[16], p1[16];
        #pragma unroll
        for (int s = 0; s < 16; s++) {
            ull t0 = 0ull, t1 = 0ull;
            #pragma unroll
            for (int i2 = 0; i2 < 4; i2++) {
                ull q = qk2[(s * 4 + i2) * 32 + lane];
                FMA2(t0, q, xv0[i2], t0);
                FMA2(t1, q, xv1[i2], t1);
            }
            UNPK2(lo, hi, t0); p0[s] = lo + hi;
            UNPK2(lo, hi, t1); p1[s] = lo + hi;
        }

        #pragma unroll
        for (int o = 16; o; o >>= 1) {
            s10 += __shfl_xor_sync(0xffffffffu, s10, o);
            s20 += __shfl_xor_sync(0xffffffffu, s20, o);
            s11 += __shfl_xor_sync(0xffffffffu, s11, o);
            s21 += __shfl_xor_sync(0xffffffffu, s21, o);
        }
        float m0 = s10 * (1.f / 256), m1 = s11 * (1.f / 256);
        float r0 = rsqrtf(s20 * (1.f / 256) - m0 * m0 + 1e-5f);
        float r1 = rsqrtf(s21 * (1.f / 256) - m1 * m1 + 1e-5f);

        float d0 = rs16(p0, lane);
        float d1 = rs16(p1, lane);
        // logit = rstd*dot - rstd*m*qsum + c (no max-subtract; |logit| bounded small)
        float e0 = __expf(fmaf(d0, r0, fmaf(-r0 * m0, qs_l, c_l)));
        float e1 = __expf(fmaf(d1, r1, fmaf(-r1 * m1, qs_l, c_l)));
        float den0 = e0, den1 = e1;
        #pragma unroll
        for (int o = 16; o; o >>= 1) {
            den0 += __shfl_xor_sync(0xffffffffu, den0, o);
            den1 += __shfl_xor_sync(0xffffffffu, den1, o);
        }
        float a0 = e0 * __fdividef(2.0f, den0);
        float a1 = e1 * __fdividef(2.0f, den1);
        float b0 = a0 * r0, b1 = a1 * r1;
        rsum += a0 + a1;
        tsum = fmaf(b0, m0, fmaf(b1, m1, tsum));

        #pragma unroll
        for (int s = 0; s < 16; s++) {
            float bv0 = __shfl_sync(0xffffffffu, b0, 2 * s);
            float bv1 = __shfl_sync(0xffffffffu, b1, 2 * s);
            ull B0p, B1p; PACK2(B0p, bv0, bv0); PACK2(B1p, bv1, bv1);
            #pragma unroll
            for (int i2 = 0; i2 < 4; i2++) {
                FMA2(acc2[s * 4 + i2], B0p, xv0[i2], acc2[s * 4 + i2]);
                FMA2(acc2[s * 4 + i2], B1p, xv1[i2], acc2[s * 4 + i2]);
            }
        }
    }

    // ---- block-level tree reduction of acc2 (8 warps -> 1) ----
    if (!(lane & 1)) { rbuf[w][lane >> 1] = rsum; tbuf[w][lane >> 1] = tsum; }
    __syncthreads();
    if (w >= 4) {
        #pragma unroll
        for (int i = 0; i < 64; i++) bufs[(w - 4) * 2048 + i * 32 + lane] = acc2[i];
    }
    __syncthreads();
    if (w < 4) {
        #pragma unroll
        for (int i = 0; i < 64; i++) {
            ull v = bufs[w * 2048 + i * 32 + lane];
            FMA2(acc2[i], v, ONE, acc2[i]);
        }
    }
    __syncthreads();
    if (w == 2 || w == 3) {
        #pragma unroll
        for (int i = 0; i < 64; i++) bufs[w * 2048 + i * 32 + lane] = acc2[i];
    }
    __syncthreads();
    if (w < 2) {
        #pragma unroll
        for (int i = 0; i < 64; i++) {
            ull v = bufs[(w + 2) * 2048 + i * 32 + lane];
            FMA2(acc2[i], v, ONE, acc2[i]);
        }
    }
    __syncthreads();
    if (w == 1) {
        #pragma unroll
        for (int i = 0; i < 64; i++) bufs[2048 + i * 32 + lane] = acc2[i];
    }
    __syncthreads();
    if (w == 0) {
        float* gp = g_part + (size_t)blockIdx.x * 4096;
        #pragma unroll
        for (int s = 0; s < 16; s++) {
            #pragma unroll
            for (int i2 = 0; i2 < 4; i2++) {
                ull v = bufs[2048 + (s * 4 + i2) * 32 + lane];
                FMA2(acc2[s * 4 + i2], v, ONE, acc2[s * 4 + i2]);
                *(ull*)(gp + s * 256 + F0(i2, lane)) = acc2[s * 4 + i2];
            }
        }
        if (lane < 16) {
            float r = 0.f, tt = 0.f;
            #pragma unroll
            for (int ww = 0; ww < 8; ww++) { r += rbuf[ww][lane]; tt += tbuf[ww][lane]; }
            g_rsA[blockIdx.x * 16 + lane] = r;
            g_tA[blockIdx.x * 16 + lane] = tt;
        }
    }
}

// ====== k_upd: reduce partials, reconstruct LN-affine, Wv GEMV ======
__global__ void k_upd(const float* __restrict__ Wv,
                      const float* __restrict__ lnf_g, const float* __restrict__ lnf_b) {
    __shared__ float red[16];
    __shared__ float shv[256];
    int s = blockIdx.x, t = threadIdx.x;
    int lane = t & 31, wid = t >> 5;

    float av = (t < NBLK_A) ? g_rsA[t * 16 + s] : 0.f;
    float tv = (t < NBLK_A) ? g_tA[t * 16 + s] : 0.f;
    #pragma unroll
    for (int o = 16; o; o >>= 1) {
        av += __shfl_xor_sync(0xffffffffu, av, o);
        tv += __shfl_xor_sync(0xffffffffu, tv, o);
    }
    if (lane == 0) { red[wid] = av; red[8 + wid] = tv; }
    __syncthreads();
    float A = 0.f, T = 0.f;
    #pragma unroll
    for (int i = 0; i < 8; i++) { A += red[i]; T += red[8 + i]; }

    const float* gp = g_part + s * 256 + t;
    float wx0 = 0.f, wx1 = 0.f, wx2 = 0.f, wx3 = 0.f;
    for (int b = 0; b < NBLK_A; b += 4) {
        wx0 += gp[(size_t)b * 4096];
        wx1 += gp[(size_t)(b + 1) * 4096];
        wx2 += gp[(size_t)(b + 2) * 4096];
        wx3 += gp[(size_t)(b + 3) * 4096];
    }
    float wx = (wx0 + wx1) + (wx2 + wx3);

    float wfeat = lnf_g[t] * (wx - T) + lnf_b[t] * A;
    shv[t] = wfeat;
    __syncthreads();

    float inv = 1.0f / (A + 1.0f);   // EPSILON = 1.0
    float a0 = 0.f, a1 = 0.f, a2 = 0.f, a3 = 0.f;
    #pragma unroll 4
    for (int f = 0; f < 256; f += 4) {
        a0 += shv[f] * Wv[f * 256 + t];
        a1 += shv[f + 1] * Wv[(f + 1) * 256 + t];
        a2 += shv[f + 2] * Wv[(f + 2) * 256 + t];
        a3 += shv[f + 3] * Wv[(f + 3) * 256 + t];
    }
    g_upd[s * 256 + t] = ((a0 + a1) + (a2 + a3)) * inv;
}

// ================= k_gates: GRU gi/gh, warp per output j =================
__global__ void k_gates(const float* __restrict__ wih, const float* __restrict__ whh,
                        const float* __restrict__ slots_init) {
    __shared__ float upd_t[4096];
    __shared__ float h_t[4096];
    int t = threadIdx.x;
    for (int idx = t; idx < 4096; idx += 256) {
        int s = idx >> 8, d = idx & 255;
        upd_t[d * 16 + s] = g_upd[idx];
        h_t[d * 16 + s] = slots_init[idx];
    }
    __syncthreads();
    int lane = t & 31, w = t >> 5;
    int j = blockIdx.x * 8 + w;
    int c = lane >> 4, s = lane & 15;
    const float* wi = wih + (size_t)j * 256 + c;
    const float* wh = whh + (size_t)j * 256 + c;
    float ai = 0.f, ah = 0.f;
    #pragma unroll 8
    for (int i = 0; i < 128; i++) {
        int d = 2 * i + c;
        ai += upd_t[d * 16 + s] * wi[2 * i];
        ah += h_t[d * 16 + s] * wh[2 * i];
    }
    ai += __shfl_xor_sync(0xffffffffu, ai, 16);
    ah += __shfl_xor_sync(0xffffffffu, ah, 16);
    if (lane < 16) {
        g_gi[j * 16 + lane] = ai;
        g_gh[j * 16 + lane] = ah;
    }
}

// ================= k_point: GRU pointwise + LN_m =================
__global__ void k_point(const float* __restrict__ slots_init,
                        const float* __restrict__ bih, const float* __restrict__ bhh,
                        const float* __restrict__ lnm_g, const float* __restrict__ lnm_b) {
    __shared__ float red[16];
    int s = blockIdx.x, t = threadIdx.x;
    float gi0 = g_gi[t * 16 + s] + bih[t];
    float gi1 = g_gi[(256 + t) * 16 + s] + bih[256 + t];
    float gi2 = g_gi[(512 + t) * 16 + s] + bih[512 + t];
    float gh0 = g_gh[t * 16 + s] + bhh[t];
    float gh1 = g_gh[(256 + t) * 16 + s] + bhh[256 + t];
    float gh2 = g_gh[(512 + t) * 16 + s] + bhh[512 + t];
    float h = slots_init[s * 256 + t];
    float r = 1.0f / (1.0f + __expf(-(gi0 + gh0)));
    float z = 1.0f / (1.0f + __expf(-(gi1 + gh1)));
    float nn = tanhf(gi2 + r * gh2);
    float hnew = (1.0f - z) * nn + z * h;
    float mean, rstd;
    block_stats256(hnew, red, mean, rstd);
    g_hnew[s * 256 + t] = hnew;
    g_hln[s * 256 + t] = (hnew - mean) * rstd * lnm_g[t] + lnm_b[t];
}

// ================= k_mlp1 =================
__global__ void k_mlp1(const float* __restrict__ w1, const float* __restrict__ b1) {
    __shared__ float hl[256];
    int s = blockIdx.x, t = threadIdx.x;
    if (t < 256) hl[t] = g_hln[s * 256 + t];
    __syncthreads();
    float a0 = b1[t], a1 = 0.f, a2 = 0.f, a3 = 0.f;
    #pragma unroll 4
    for (int d = 0; d < 256; d += 4) {
        a0 += hl[d] * w1[d * 512 + t];
        a1 += hl[d + 1] * w1[(d + 1) * 512 + t];
        a2 += hl[d + 2] * w1[(d + 2) * 512 + t];
        a3 += hl[d + 3] * w1[(d + 3) * 512 + t];
    }
    g_hid[s * 512 + t] = fmaxf((a0 + a1) + (a2 + a3), 0.f);
}

// ============ k_mlp2: residual; write slots; LN_s; q -> g_qT ============
__global__ void k_mlp2(const float* __restrict__ w2, const float* __restrict__ b2p,
                       const float* __restrict__ lns_g, const float* __restrict__ lns_b,
                       const float* __restrict__ Wq, float* __restrict__ out_slots) {
    __shared__ float hid[512];
    __shared__ float red[16];
    __shared__ float sv[256];
    int s = blockIdx.x, t = threadIdx.x;
    hid[t] = g_hid[s * 512 + t];
    hid[256 + t] = g_hid[s * 512 + 256 + t];
    __syncthreads();
    float a0 = b2p[t], a1 = 0.f, a2 = 0.f, a3 = 0.f;
    #pragma unroll 4
    for (int r = 0; r < 512; r += 4) {
        a0 += hid[r] * w2[r * 256 + t];
        a1 += hid[r + 1] * w2[(r + 1) * 256 + t];
        a2 += hid[r + 2] * w2[(r + 2) * 256 + t];
        a3 += hid[r + 3] * w2[(r + 3) * 256 + t];
    }
    float sf = g_hnew[s * 256 + t] + ((a0 + a1) + (a2 + a3));
    out_slots[s * 256 + t] = sf;
    float mean, rstd;
    block_stats256(sf, red, mean, rstd);
    sv[t] = (sf - mean) * rstd * lns_g[t] + lns_b[t];
    __syncthreads();
    float q0 = 0.f, q1 = 0.f, q2 = 0.f, q3 = 0.f;
    #pragma unroll 4
    for (int d = 0; d < 256; d += 4) {
        q0 += sv[d] * Wq[d * 256 + t];
        q1 += sv[d + 1] * Wq[(d + 1) * 256 + t];
        q2 += sv[d + 2] * Wq[(d + 2) * 256 + t];
        q3 += sv[d + 3] * Wq[(d + 3) * 256 + t];
    }
    g_qT[t * 16 + s] = (q0 + q1) + (q2 + q3);
}

// ========== pass D: pair layout, grid 592, free regs, raw-x math (R8 proven) ==========
__global__ void __launch_bounds__(256)
k_pass_d(const float* __restrict__ features, float* __restrict__ out_attn) {
    __shared__ ull qk2[2048];
    int t = threadIdx.x;
    for (int idx = t; idx < 2048; idx += 256) {
        int s = idx >> 7, r = idx & 127, i2 = r >> 5, ln = r & 31;
        int f0 = F0(i2, ln);
        ull v; PACK2(v, g_qk[s * 256 + f0], g_qk[s * 256 + f0 + 1]);
        qk2[idx] = v;
    }
    __syncthreads();

    int lane = t & 31, w = t >> 5;
    int gw = blockIdx.x * 8 + w;
    int nw = gridDim.x * 8;
    int sl = (lane >> 1) & 15;
    float qs_l = g_qsum[sl];
    float c_l  = g_c[sl];
    ull ONE; PACK2(ONE, 1.0f, 1.0f);

    for (int pi = gw; pi < NROWS / 2; pi += nw) {
        const float4* fr = (const float4*)(features + (size_t)(2 * pi) * 256);
        float4 A0 = fr[lane], B0 = fr[32 + lane];
        float4 A1 = fr[64 + lane], B1 = fr[96 + lane];
        ull xv0[4] = { ((ull*)&A0)[0], ((ull*)&A0)[1], ((ull*)&B0)[0], ((ull*)&B0)[1] };
        ull xv1[4] = { ((ull*)&A1)[0], ((ull*)&A1)[1], ((ull*)&B1)[0], ((ull*)&B1)[1] };

        ull sp0, sq0 = 0ull, sp1, sq1 = 0ull;
        FMA2(sp0, xv0[0], ONE, xv0[1]);
        { ull tmp; FMA2(tmp, xv0[2], ONE, xv0[3]); FMA2(sp0, tmp, ONE, sp0); }
        FMA2(sp1, xv1[0], ONE, xv1[1]);
        { ull tmp; FMA2(tmp, xv1[2], ONE, xv1[3]); FMA2(sp1, tmp, ONE, sp1); }
        #pragma unroll
        for (int i = 0; i < 4; i++) { FMA2(sq0, xv0[i], xv0[i], sq0); FMA2(sq1, xv1[i], xv1[i], sq1); }
        float lo, hi, s10, s20, s11, s21;
        UNPK2(lo, hi, sp0); s10 = lo + hi;
        UNPK2(lo, hi, sq0); s20 = lo + hi;
        UNPK2(lo, hi, sp1); s11 = lo + hi;
        UNPK2(lo, hi, sq1); s21 = lo + hi;

        float p0[16], p1[16];
        #pragma unroll
        for (int s = 0; s < 16; s++) {
            ull t0 = 0ull, t1 = 0ull;
            #pragma unroll
            for (int i2 = 0; i2 < 4; i2++) {
                ull q = qk2[(s * 4 + i2) * 32 + lane];
                FMA2(t0, q, xv0[i2], t0);
                FMA2(t1, q, xv1[i2], t1);
            }
            UNPK2(lo, hi, t0); p0[s] = lo + hi;
            UNPK2(lo, hi, t1); p1[s] = lo + hi;
        }

        #pragma unroll
        for (int o = 16; o; o >>= 1) {
            s10 += __shfl_xor_sync(0xffffffffu, s10, o);
            s20 += __shfl_xor_sync(0xffffffffu, s20, o);
            s11 += __shfl_xor_sync(0xffffffffu, s11, o);
            s21 += __shfl_xor_sync(0xffffffffu, s21, o);
        }
        float m0 = s10 * (1.f / 256), m1 = s11 * (1.f / 256);
        float r0 = rsqrtf(s20 * (1.f / 256) - m0 * m0 + 1e-5f);
        float r1 = rsqrtf(s21 * (1.f / 256) - m1 * m1 + 1e-5f);

        float d0 = rs16(p0, lane);
        float d1 = rs16(p1, lane);
        float e0 = __expf(fmaf(d0, r0, fmaf(-r0 * m0, qs_l, c_l)));
        float e1 = __expf(fmaf(d1, r1, fmaf(-r1 * m1, qs_l, c_l)));
        float den0 = e0, den1 = e1;
        #pragma unroll
        for (int o = 16; o; o >>= 1) {
            den0 += __shfl_xor_sync(0xffffffffu, den0, o);
            den1 += __shfl_xor_sync(0xffffffffu, den1, o);
        }
        float a0 = e0 * __fdividef(2.0f, den0);
        float a1 = e1 * __fdividef(2.0f, den1);

        float outv = (lane & 1) ? a1 : a0;
        out_attn[(size_t)(2 * pi + (lane & 1)) * 16 + sl] = outv;
    }
}

// ================= launcher =================
extern "C" void kernel_launch(void* const* d_in, const int* in_sizes, int n_in,
                              void* d_out, int out_size) {
    const float* features   = (const float*)d_in[0];
    const float* ln_f_g     = (const float*)d_in[1];
    const float* ln_f_b     = (const float*)d_in[2];
    const float* ln_s_g     = (const float*)d_in[3];
    const float* ln_s_b     = (const float*)d_in[4];
    const float* ln_m_g     = (const float*)d_in[5];
    const float* ln_m_b     = (const float*)d_in[6];
    const float* Wq         = (const float*)d_in[7];
    const float* Wk         = (const float*)d_in[8];
    const float* Wv         = (const float*)d_in[9];
    const float* gru_wih    = (const float*)d_in[10];
    const float* gru_whh    = (const float*)d_in[11];
    const float* gru_bih    = (const float*)d_in[12];
    const float* gru_bhh    = (const float*)d_in[13];
    const float* mlp_w1     = (const float*)d_in[14];
    const float* mlp_b1     = (const float*)d_in[15];
    const float* mlp_w2     = (const float*)d_in[16];
    const float* mlp_b2     = (const float*)d_in[17];
    const float* slots_init = (const float*)d_in[18];
    // d_in[19] = num_iter (fixed at 2 -> exactly one update iteration)

    float* out = (float*)d_out;   // [0:4096) slots, [4096:) attn [N,16]

    const int DYN_A = 5 * 2048 * sizeof(ull);  // 80KB
    cudaFuncSetAttribute(k_pass_a, cudaFuncAttributeMaxDynamicSharedMemorySize, DYN_A);

    // warm L2 for the prep chain (Wq, Wk, slots_init)
    k_pref<<<64, 256>>>((const float4*)Wq, 16384, (const float4*)Wk, 16384,
                        (const float4*)slots_init, 1024,
                        (const float4*)0, 0, (const float4*)0, 0,
                        (const float4*)0, 0, (const float4*)0, 0);
    k_prep<<<KSLOT, 256>>>(slots_init, ln_s_g, ln_s_b, Wq);
    k_qk<<<16, 256>>>(Wk, ln_f_g, ln_f_b);
    k_qfin<<<1, 512>>>();
    k_pass_a<<<NBLK_A, 256, DYN_A>>>(features);
    // pass A streamed 128MB through L2 -> re-warm all mid-chain weights now
    k_pref<<<148, 256>>>((const float4*)Wv, 16384,
                         (const float4*)gru_wih, 49152, (const float4*)gru_whh, 49152,
                         (const float4*)mlp_w1, 32768, (const float4*)mlp_w2, 32768,
                         (const float4*)Wq, 16384, (const float4*)Wk, 16384);
    k_upd<<<KSLOT, 256>>>(Wv, ln_f_g, ln_f_b);
    k_gates<<<96, 256>>>(gru_wih, gru_whh, slots_init);
    k_point<<<KSLOT, 256>>>(slots_init, gru_bih, gru_bhh, ln_m_g, ln_m_b);
    k_mlp1<<<KSLOT, 512>>>(mlp_w1, mlp_b1);
    k_mlp2<<<KSLOT, 256>>>(mlp_w2, mlp_b2, ln_s_g, ln_s_b, Wq, out);
    k_qk<<<16, 256>>>(Wk, ln_f_g, ln_f_b);
    k_qfin<<<1, 512>>>();
    k_pass_d<<<592, 256>>>(features, out + KSLOT * 256);
}

// round 13
// speedup vs baseline: 1.2375x; 1.0502x over previous
#include <cuda_runtime.h>
#include <math.h>

typedef unsigned long long ull;

// Problem constants
#define NROWS 131072
#define KSLOT 16
#define NBLK_A 148
#define NWARP_A (NBLK_A * 8)      // 1184

// -------- device scratch (static) --------
__device__ float g_qk[KSLOT * 256];     // qkg[s][f] = qk * gamma_f, scale folded
__device__ float g_qsP[256];            // per-block partial qsum [s*16+b]
__device__ float g_cP[256];             // per-block partial c    [s*16+b]
__device__ float g_qT[256 * KSLOT];     // q transposed [d][s]
__device__ float g_part[NBLK_A * KSLOT * 256];   // per-block wx partials (2.4MB)
__device__ float g_rsA[NBLK_A * KSLOT];          // per-block A_s partials
__device__ float g_tA[NBLK_A * KSLOT];           // per-block t_s partials
__device__ float g_upd[KSLOT * 256];
__device__ float g_gi[768 * KSLOT];
__device__ float g_gh[768 * KSLOT];
__device__ float g_sink[256];           // prefetch sink (not an output)

// -------- f32x2 packed helpers --------
#define FMA2(d,a,b,c) asm("fma.rn.f32x2 %0, %1, %2, %3;" : "=l"(d) : "l"(a), "l"(b), "l"(c))
#define PACK2(d,lo,hi) asm("mov.b64 %0, {%1, %2};" : "=l"(d) : "r"(__float_as_uint(lo)), "r"(__float_as_uint(hi)))
#define UNPK2(lo,hi,src) do { unsigned _ul,_uh; \
    asm("mov.b64 {%0, %1}, %2;" : "=r"(_ul), "=r"(_uh) : "l"(src)); \
    lo = __uint_as_float(_ul); hi = __uint_as_float(_uh); } while(0)

// feature index owned by (i2, lane): pairs (F0, F0+1)
__device__ __forceinline__ int F0(int i2, int lane) {
    return (i2 >> 1) * 128 + 4 * lane + 2 * (i2 & 1);
}

// -------- warp helpers --------
// reduce-scatter 16 values across 32 lanes; returns sum for s=(lane>>1)&15
__device__ __forceinline__ float rs16(const float* v, int lane) {
    bool b4 = (lane & 16) != 0, b3 = (lane & 8) != 0, bb2 = (lane & 4) != 0, bb1 = (lane & 2) != 0;
    float w[8];
    #pragma unroll
    for (int i = 0; i < 8; i++) {
        float snd = b4 ? v[i] : v[i + 8];
        float kp  = b4 ? v[i + 8] : v[i];
        w[i] = kp + __shfl_xor_sync(0xffffffffu, snd, 16);
    }
    float u[4];
    #pragma unroll
    for (int i = 0; i < 4; i++) {
        float snd = b3 ? w[i] : w[i + 4];
        float kp  = b3 ? w[i + 4] : w[i];
        u[i] = kp + __shfl_xor_sync(0xffffffffu, snd, 8);
    }
    float x[2];
    #pragma unroll
    for (int i = 0; i < 2; i++) {
        float snd = bb2 ? u[i] : u[i + 2];
        float kp  = bb2 ? u[i + 2] : u[i];
        x[i] = kp + __shfl_xor_sync(0xffffffffu, snd, 4);
    }
    float snd = bb1 ? x[0] : x[1];
    float kp  = bb1 ? x[1] : x[0];
    float r = kp + __shfl_xor_sync(0xffffffffu, snd, 2);
    r += __shfl_xor_sync(0xffffffffu, r, 1);
    return r;
}

// block of 256 threads: mean + rstd of one 256-vector
__device__ __forceinline__ void block_stats256(float v, float* red, float& mean, float& rstd) {
    float s1 = v, s2 = v * v;
    #pragma unroll
    for (int o = 16; o; o >>= 1) {
        s1 += __shfl_xor_sync(0xffffffffu, s1, o);
        s2 += __shfl_xor_sync(0xffffffffu, s2, o);
    }
    int w = threadIdx.x >> 5;
    if ((threadIdx.x & 31) == 0) { red[w] = s1; red[8 + w] = s2; }
    __syncthreads();
    s1 = 0.f; s2 = 0.f;
    #pragma unroll
    for (int i = 0; i < 8; i++) { s1 += red[i]; s2 += red[8 + i]; }
    mean = s1 * (1.0f / 256.0f);
    float var = s2 * (1.0f / 256.0f) - mean * mean;
    rstd = rsqrtf(var + 1e-5f);
    __syncthreads();
}

// 512-thread block: stats over the 256 values held by threads t<256
__device__ __forceinline__ void stats256_512(float v, int t, float* red, float& mean, float& rstd) {
    bool act = t < 256;
    float s1 = act ? v : 0.f, s2 = act ? v * v : 0.f;
    #pragma unroll
    for (int o = 16; o; o >>= 1) {
        s1 += __shfl_xor_sync(0xffffffffu, s1, o);
        s2 += __shfl_xor_sync(0xffffffffu, s2, o);
    }
    int w = t >> 5;
    if ((t & 31) == 0) { red[w] = s1; red[16 + w] = s2; }
    __syncthreads();
    s1 = 0.f; s2 = 0.f;
    #pragma unroll
    for (int i = 0; i < 8; i++) { s1 += red[i]; s2 += red[16 + i]; }
    mean = s1 * (1.0f / 256.0f);
    float var = s2 * (1.0f / 256.0f) - mean * mean;
    rstd = rsqrtf(var + 1e-5f);
    __syncthreads();
}

// reduce g_qsP/g_cP partials in a 256-thread block -> qs_sh[16], c_sh[16]
__device__ __forceinline__ void reduce_qparts(int t, float* qs_sh, float* c_sh) {
    float v1 = g_qsP[t];   // t = s*16 + b
    float v2 = g_cP[t];
    #pragma unroll
    for (int o = 8; o; o >>= 1) {
        v1 += __shfl_xor_sync(0xffffffffu, v1, o);
        v2 += __shfl_xor_sync(0xffffffffu, v2, o);
    }
    if ((t & 15) == 0) { qs_sh[t >> 4] = v1; c_sh[t >> 4] = v2; }
}

// ================= k_pref: warm L2 with weight tensors (sum -> sink) ==============
__global__ void k_pref(const float4* __restrict__ p0, int n0,
                       const float4* __restrict__ p1, int n1,
                       const float4* __restrict__ p2, int n2,
                       const float4* __restrict__ p3, int n3,
                       const float4* __restrict__ p4, int n4,
                       const float4* __restrict__ p5, int n5,
                       const float4* __restrict__ p6, int n6) {
    int stride = gridDim.x * blockDim.x;
    int i0 = blockIdx.x * blockDim.x + threadIdx.x;
    float s = 0.f;
    for (int i = i0; i < n0; i += stride) { float4 v = p0[i]; s += (v.x + v.y) + (v.z + v.w); }
    for (int i = i0; i < n1; i += stride) { float4 v = p1[i]; s += (v.x + v.y) + (v.z + v.w); }
    for (int i = i0; i < n2; i += stride) { float4 v = p2[i]; s += (v.x + v.y) + (v.z + v.w); }
    for (int i = i0; i < n3; i += stride) { float4 v = p3[i]; s += (v.x + v.y) + (v.z + v.w); }
    for (int i = i0; i < n4; i += stride) { float4 v = p4[i]; s += (v.x + v.y) + (v.z + v.w); }
    for (int i = i0; i < n5; i += stride) { float4 v = p5[i]; s += (v.x + v.y) + (v.z + v.w); }
    for (int i = i0; i < n6; i += stride) { float4 v = p6[i]; s += (v.x + v.y) + (v.z + v.w); }
    g_sink[i0 & 255] = s;   // scratch sink (not program output)
}

// ================= k_prep: LN(slots_init) @ Wq -> g_qT =================
__global__ void k_prep(const float* __restrict__ slots_init,
                       const float* __restrict__ ln_s_g, const float* __restrict__ ln_s_b,
                       const float* __restrict__ Wq) {
    __shared__ float red[16];
    __shared__ float sv[256];
    int s = blockIdx.x, t = threadIdx.x;
    float v = slots_init[s * 256 + t];
    float mean, rstd;
    block_stats256(v, red, mean, rstd);
    sv[t] = (v - mean) * rstd * ln_s_g[t] + ln_s_b[t];
    __syncthreads();
    float a0 = 0.f, a1 = 0.f, a2 = 0.f, a3 = 0.f;
    #pragma unroll 4
    for (int d = 0; d < 256; d += 4) {
        a0 += sv[d] * Wq[d * 256 + t];
        a1 += sv[d + 1] * Wq[(d + 1) * 256 + t];
        a2 += sv[d + 2] * Wq[(d + 2) * 256 + t];
        a3 += sv[d + 3] * Wq[(d + 3) * 256 + t];
    }
    g_qT[t * 16 + s] = (a0 + a1) + (a2 + a3);
}

// ====== k_qk (smem-staged): qkg[s][f] = (q[s].Wk[f])/16 * gamma_f ; + partial sums ======
// 16 blocks; block b covers f in [16b, 16b+16). Writes g_qsP/g_cP partials (replaces k_qfin).
__global__ void k_qk(const float* __restrict__ Wk,
                     const float* __restrict__ lnf_g, const float* __restrict__ lnf_b) {
    __shared__ float qT[4096];
    __shared__ float wk_sh[4096];
    __shared__ float rq[256], rc[256];
    int t = threadIdx.x, b = blockIdx.x;
    for (int idx = t; idx < 4096; idx += 256) {
        qT[idx] = g_qT[idx];
        wk_sh[idx] = Wk[b * 4096 + idx];   // rows 16b..16b+15, contiguous
    }
    __syncthreads();
    int fi = t >> 4, s = t & 15;
    int f = b * 16 + fi;
    const float* wr = wk_sh + fi * 256;
    float a0 = 0.f, a1 = 0.f, a2 = 0.f, a3 = 0.f;
    #pragma unroll 4
    for (int d = 0; d < 256; d += 4) {
        a0 += qT[d * 16 + s] * wr[d];
        a1 += qT[(d + 1) * 16 + s] * wr[d + 1];
        a2 += qT[(d + 2) * 16 + s] * wr[d + 2];
        a3 += qT[(d + 3) * 16 + s] * wr[d + 3];
    }
    float af = ((a0 + a1) + (a2 + a3)) * 0.0625f;   // scale = D^-0.5
    float qkg = af * lnf_g[f];
    g_qk[s * 256 + f] = qkg;
    rq[fi * 16 + s] = qkg;
    rc[fi * 16 + s] = af * lnf_b[f];
    __syncthreads();
    if (t < 16) {
        float sq = 0.f, sc = 0.f;
        #pragma unroll
        for (int i = 0; i < 16; i++) { sq += rq[i * 16 + t]; sc += rc[i * 16 + t]; }
        g_qsP[t * 16 + b] = sq;
        g_cP[t * 16 + b] = sc;
    }
}

// ================= pass A: raw-x logits + softmax + rank-16 accum =================
__global__ void __launch_bounds__(256, 1)
k_pass_a(const float* __restrict__ features) {
    extern __shared__ ull dyn[];
    ull* qk2 = dyn;                 // 2048 ull (16KB)
    ull* bufs = dyn + 2048;         // 4 * 2048 ull (64KB)
    __shared__ float rbuf[8][16], tbuf[8][16];
    __shared__ float qs_sh[16], c_sh[16];

    int t = threadIdx.x;
    for (int idx = t; idx < 2048; idx += 256) {
        int s = idx >> 7, r = idx & 127, i2 = r >> 5, ln = r & 31;
        int f0 = F0(i2, ln);
        ull v; PACK2(v, g_qk[s * 256 + f0], g_qk[s * 256 + f0 + 1]);
        qk2[idx] = v;
    }
    reduce_qparts(t, qs_sh, c_sh);
    __syncthreads();

    int lane = t & 31, w = t >> 5;
    int gw = blockIdx.x * 8 + w;
    int sl = (lane >> 1) & 15;
    float qs_l = qs_sh[sl];
    float c_l  = c_sh[sl];
    ull ONE; PACK2(ONE, 1.0f, 1.0f);

    ull acc2[64];
    #pragma unroll
    for (int i = 0; i < 64; i++) acc2[i] = 0ull;
    float rsum = 0.f, tsum = 0.f;

    for (int pi = gw; pi < NROWS / 2; pi += NWARP_A) {
        const float4* fr = (const float4*)(features + (size_t)(2 * pi) * 256);
        float4 A0 = fr[lane], B0 = fr[32 + lane];
        float4 A1 = fr[64 + lane], B1 = fr[96 + lane];
        ull xv0[4] = { ((ull*)&A0)[0], ((ull*)&A0)[1], ((ull*)&B0)[0], ((ull*)&B0)[1] };
        ull xv1[4] = { ((ull*)&A1)[0], ((ull*)&A1)[1], ((ull*)&B1)[0], ((ull*)&B1)[1] };

        // stats on raw x (packed)
        ull sp0, sq0 = 0ull, sp1, sq1 = 0ull;
        FMA2(sp0, xv0[0], ONE, xv0[1]);
        { ull tmp; FMA2(tmp, xv0[2], ONE, xv0[3]); FMA2(sp0, tmp, ONE, sp0); }
        FMA2(sp1, xv1[0], ONE, xv1[1]);
        { ull tmp; FMA2(tmp, xv1[2], ONE, xv1[3]); FMA2(sp1, tmp, ONE, sp1); }
        #pragma unroll
        for (int i = 0; i < 4; i++) { FMA2(sq0, xv0[i], xv0[i], sq0); FMA2(sq1, xv1[i], xv1[i], sq1); }
        float lo, hi, s10, s20, s11, s21;
        UNPK2(lo, hi, sp0); s10 = lo + hi;
        UNPK2(lo, hi, sq0); s20 = lo + hi;
        UNPK2(lo, hi, sp1); s11 = lo + hi;
        UNPK2(lo, hi, sq1); s21 = lo + hi;

        // logits dot on raw x (independent of stats -> overlaps)
        float p0[16], p1[16];
        #pragma unroll
        for (int s = 0; s < 16; s++) {
            ull t0 = 0ull, t1 = 0ull;
            #pragma unroll
            for (int i2 = 0; i2 < 4; i2++) {
                ull q = qk2[(s * 4 + i2) * 32 + lane];
                FMA2(t0, q, xv0[i2], t0);
                FMA2(t1, q, xv1[i2], t1);
            }
            UNPK2(lo, hi, t0); p0[s] = lo + hi;
            UNPK2(lo, hi, t1); p1[s] = lo + hi;
        }

        #pragma unroll
        for (int o = 16; o; o >>= 1) {
            s10 += __shfl_xor_sync(0xffffffffu, s10, o);
            s20 += __shfl_xor_sync(0xffffffffu, s20, o);
            s11 += __shfl_xor_sync(0xffffffffu, s11, o);
            s21 += __shfl_xor_sync(0xffffffffu, s21, o);
        }
        float m0 = s10 * (1.f / 256), m1 = s11 * (1.f / 256);
        float r0 = rsqrtf(s20 * (1.f / 256) - m0 * m0 + 1e-5f);
        float r1 = rsqrtf(s21 * (1.f / 256) - m1 * m1 + 1e-5f);

        float d0 = rs16(p0, lane);
        float d1 = rs16(p1, lane);
        // logit = rstd*dot - rstd*m*qsum + c (no max-subtract; |logit| bounded small)
        float e0 = __expf(fmaf(d0, r0, fmaf(-r0 * m0, qs_l, c_l)));
        float e1 = __expf(fmaf(d1, r1, fmaf(-r1 * m1, qs_l, c_l)));
        float den0 = e0, den1 = e1;
        #pragma unroll
        for (int o = 16; o; o >>= 1) {
            den0 += __shfl_xor_sync(0xffffffffu, den0, o);
            den1 += __shfl_xor_sync(0xffffffffu, den1, o);
        }
        float a0 = e0 * __fdividef(2.0f, den0);
        float a1 = e1 * __fdividef(2.0f, den1);
        float b0 = a0 * r0, b1 = a1 * r1;
        rsum += a0 + a1;
        tsum = fmaf(b0, m0, fmaf(b1, m1, tsum));

        #pragma unroll
        for (int s = 0; s < 16; s++) {
            float bv0 = __shfl_sync(0xffffffffu, b0, 2 * s);
            float bv1 = __shfl_sync(0xffffffffu, b1, 2 * s);
            ull B0p, B1p; PACK2(B0p, bv0, bv0); PACK2(B1p, bv1, bv1);
            #pragma unroll
            for (int i2 = 0; i2 < 4; i2++) {
                FMA2(acc2[s * 4 + i2], B0p, xv0[i2], acc2[s * 4 + i2]);
                FMA2(acc2[s * 4 + i2], B1p, xv1[i2], acc2[s * 4 + i2]);
            }
        }
    }

    // ---- block-level tree reduction of acc2 (8 warps -> 1) ----
    if (!(lane & 1)) { rbuf[w][lane >> 1] = rsum; tbuf[w][lane >> 1] = tsum; }
    __syncthreads();
    if (w >= 4) {
        #pragma unroll
        for (int i = 0; i < 64; i++) bufs[(w - 4) * 2048 + i * 32 + lane] = acc2[i];
    }
    __syncthreads();
    if (w < 4) {
        #pragma unroll
        for (int i = 0; i < 64; i++) {
            ull v = bufs[w * 2048 + i * 32 + lane];
            FMA2(acc2[i], v, ONE, acc2[i]);
        }
    }
    __syncthreads();
    if (w == 2 || w == 3) {
        #pragma unroll
        for (int i = 0; i < 64; i++) bufs[w * 2048 + i * 32 + lane] = acc2[i];
    }
    __syncthreads();
    if (w < 2) {
        #pragma unroll
        for (int i = 0; i < 64; i++) {
            ull v = bufs[(w + 2) * 2048 + i * 32 + lane];
            FMA2(acc2[i], v, ONE, acc2[i]);
        }
    }
    __syncthreads();
    if (w == 1) {
        #pragma unroll
        for (int i = 0; i < 64; i++) bufs[2048 + i * 32 + lane] = acc2[i];
    }
    __syncthreads();
    if (w == 0) {
        float* gp = g_part + (size_t)blockIdx.x * 4096;
        #pragma unroll
        for (int s = 0; s < 16; s++) {
            #pragma unroll
            for (int i2 = 0; i2 < 4; i2++) {
                ull v = bufs[2048 + (s * 4 + i2) * 32 + lane];
                FMA2(acc2[s * 4 + i2], v, ONE, acc2[s * 4 + i2]);
                *(ull*)(gp + s * 256 + F0(i2, lane)) = acc2[s * 4 + i2];
            }
        }
        if (lane < 16) {
            float r = 0.f, tt = 0.f;
            #pragma unroll
            for (int ww = 0; ww < 8; ww++) { r += rbuf[ww][lane]; tt += tbuf[ww][lane]; }
            g_rsA[blockIdx.x * 16 + lane] = r;
            g_tA[blockIdx.x * 16 + lane] = tt;
        }
    }
}

// ====== k_upd: reduce partials, reconstruct LN-affine, Wv GEMV ======
__global__ void k_upd(const float* __restrict__ Wv,
                      const float* __restrict__ lnf_g, const float* __restrict__ lnf_b) {
    __shared__ float red[16];
    __shared__ float shv[256];
    int s = blockIdx.x, t = threadIdx.x;
    int lane = t & 31, wid = t >> 5;

    float av = (t < NBLK_A) ? g_rsA[t * 16 + s] : 0.f;
    float tv = (t < NBLK_A) ? g_tA[t * 16 + s] : 0.f;
    #pragma unroll
    for (int o = 16; o; o >>= 1) {
        av += __shfl_xor_sync(0xffffffffu, av, o);
        tv += __shfl_xor_sync(0xffffffffu, tv, o);
    }
    if (lane == 0) { red[wid] = av; red[8 + wid] = tv; }
    __syncthreads();
    float A = 0.f, T = 0.f;
    #pragma unroll
    for (int i = 0; i < 8; i++) { A += red[i]; T += red[8 + i]; }

    const float* gp = g_part + s * 256 + t;
    float wx0 = 0.f, wx1 = 0.f, wx2 = 0.f, wx3 = 0.f;
    for (int b = 0; b < NBLK_A; b += 4) {
        wx0 += gp[(size_t)b * 4096];
        wx1 += gp[(size_t)(b + 1) * 4096];
        wx2 += gp[(size_t)(b + 2) * 4096];
        wx3 += gp[(size_t)(b + 3) * 4096];
    }
    float wx = (wx0 + wx1) + (wx2 + wx3);

    float wfeat = lnf_g[t] * (wx - T) + lnf_b[t] * A;
    shv[t] = wfeat;
    __syncthreads();

    float inv = 1.0f / (A + 1.0f);   // EPSILON = 1.0
    float a0 = 0.f, a1 = 0.f, a2 = 0.f, a3 = 0.f;
    #pragma unroll 4
    for (int f = 0; f < 256; f += 4) {
        a0 += shv[f] * Wv[f * 256 + t];
        a1 += shv[f + 1] * Wv[(f + 1) * 256 + t];
        a2 += shv[f + 2] * Wv[(f + 2) * 256 + t];
        a3 += shv[f + 3] * Wv[(f + 3) * 256 + t];
    }
    g_upd[s * 256 + t] = ((a0 + a1) + (a2 + a3)) * inv;
}

// ================= k_gates: GRU gi/gh, warp per output j =================
__global__ void k_gates(const float* __restrict__ wih, const float* __restrict__ whh,
                        const float* __restrict__ slots_init) {
    __shared__ float upd_t[4096];
    __shared__ float h_t[4096];
    int t = threadIdx.x;
    for (int idx = t; idx < 4096; idx += 256) {
        int s = idx >> 8, d = idx & 255;
        upd_t[d * 16 + s] = g_upd[idx];
        h_t[d * 16 + s] = slots_init[idx];
    }
    __syncthreads();
    int lane = t & 31, w = t >> 5;
    int j = blockIdx.x * 8 + w;
    int c = lane >> 4, s = lane & 15;
    const float* wi = wih + (size_t)j * 256 + c;
    const float* wh = whh + (size_t)j * 256 + c;
    float ai = 0.f, ah = 0.f;
    #pragma unroll 8
    for (int i = 0; i < 128; i++) {
        int d = 2 * i + c;
        ai += upd_t[d * 16 + s] * wi[2 * i];
        ah += h_t[d * 16 + s] * wh[2 * i];
    }
    ai += __shfl_xor_sync(0xffffffffu, ai, 16);
    ah += __shfl_xor_sync(0xffffffffu, ah, 16);
    if (lane < 16) {
        g_gi[j * 16 + lane] = ai;
        g_gh[j * 16 + lane] = ah;
    }
}

// ====== k_tail: GRU pointwise + LN_m + MLP(residual) + out_slots + LN_s + qproj ======
__global__ void __launch_bounds__(512)
k_tail(const float* __restrict__ slots_init,
       const float* __restrict__ bih, const float* __restrict__ bhh,
       const float* __restrict__ lnm_g, const float* __restrict__ lnm_b,
       const float* __restrict__ w1, const float* __restrict__ b1,
       const float* __restrict__ w2, const float* __restrict__ b2p,
       const float* __restrict__ lns_g, const float* __restrict__ lns_b,
       const float* __restrict__ Wq, float* __restrict__ out_slots) {
    __shared__ float red[32];
    __shared__ float hl[256];
    __shared__ float hid[512];
    __shared__ float sv[256];
    int s = blockIdx.x, t = threadIdx.x;

    float hnew = 0.f;
    if (t < 256) {
        float gi0 = g_gi[t * 16 + s] + bih[t];
        float gi1 = g_gi[(256 + t) * 16 + s] + bih[256 + t];
        float gi2 = g_gi[(512 + t) * 16 + s] + bih[512 + t];
        float gh0 = g_gh[t * 16 + s] + bhh[t];
        float gh1 = g_gh[(256 + t) * 16 + s] + bhh[256 + t];
        float gh2 = g_gh[(512 + t) * 16 + s] + bhh[512 + t];
        float h = slots_init[s * 256 + t];
        float r = 1.0f / (1.0f + __expf(-(gi0 + gh0)));
        float z = 1.0f / (1.0f + __expf(-(gi1 + gh1)));
        float nn = tanhf(gi2 + r * gh2);
        hnew = (1.0f - z) * nn + z * h;
    }
    float mean, rstd;
    stats256_512(hnew, t, red, mean, rstd);
    if (t < 256) hl[t] = (hnew - mean) * rstd * lnm_g[t] + lnm_b[t];
    __syncthreads();

    // mlp1: all 512 threads, one output each
    float a0 = b1[t], a1 = 0.f, a2 = 0.f, a3 = 0.f;
    #pragma unroll 4
    for (int d = 0; d < 256; d += 4) {
        a0 += hl[d] * w1[d * 512 + t];
        a1 += hl[d + 1] * w1[(d + 1) * 512 + t];
        a2 += hl[d + 2] * w1[(d + 2) * 512 + t];
        a3 += hl[d + 3] * w1[(d + 3) * 512 + t];
    }
    hid[t] = fmaxf((a0 + a1) + (a2 + a3), 0.f);
    __syncthreads();

    // mlp2 + residual: t<256
    float sf = 0.f;
    if (t < 256) {
        float o0 = b2p[t], o1 = 0.f, o2 = 0.f, o3 = 0.f;
        #pragma unroll 4
        for (int r = 0; r < 512; r += 4) {
            o0 += hid[r] * w2[r * 256 + t];
            o1 += hid[r + 1] * w2[(r + 1) * 256 + t];
            o2 += hid[r + 2] * w2[(r + 2) * 256 + t];
            o3 += hid[r + 3] * w2[(r + 3) * 256 + t];
        }
        sf = hnew + ((o0 + o1) + (o2 + o3));
        out_slots[s * 256 + t] = sf;
    }
    stats256_512(sf, t, red, mean, rstd);
    if (t < 256) sv[t] = (sf - mean) * rstd * lns_g[t] + lns_b[t];
    __syncthreads();

    if (t < 256) {
        float q0 = 0.f, q1 = 0.f, q2 = 0.f, q3 = 0.f;
        #pragma unroll 4
        for (int d = 0; d < 256; d += 4) {
            q0 += sv[d] * Wq[d * 256 + t];
            q1 += sv[d + 1] * Wq[(d + 1) * 256 + t];
            q2 += sv[d + 2] * Wq[(d + 2) * 256 + t];
            q3 += sv[d + 3] * Wq[(d + 3) * 256 + t];
        }
        g_qT[t * 16 + s] = (q0 + q1) + (q2 + q3);
    }
}

// ========== pass D: pair layout, grid 592, free regs, raw-x math (R8/R12 proven) ==========
__global__ void __launch_bounds__(256)
k_pass_d(const float* __restrict__ features, float* __restrict__ out_attn) {
    __shared__ ull qk2[2048];
    __shared__ float qs_sh[16], c_sh[16];
    int t = threadIdx.x;
    for (int idx = t; idx < 2048; idx += 256) {
        int s = idx >> 7, r = idx & 127, i2 = r >> 5, ln = r & 31;
        int f0 = F0(i2, ln);
        ull v; PACK2(v, g_qk[s * 256 + f0], g_qk[s * 256 + f0 + 1]);
        qk2[idx] = v;
    }
    reduce_qparts(t, qs_sh, c_sh);
    __syncthreads();

    int lane = t & 31, w = t >> 5;
    int gw = blockIdx.x * 8 + w;
    int nw = gridDim.x * 8;
    int sl = (lane >> 1) & 15;
    float qs_l = qs_sh[sl];
    float c_l  = c_sh[sl];
    ull ONE; PACK2(ONE, 1.0f, 1.0f);

    for (int pi = gw; pi < NROWS / 2; pi += nw) {
        const float4* fr = (const float4*)(features + (size_t)(2 * pi) * 256);
        float4 A0 = fr[lane], B0 = fr[32 + lane];
        float4 A1 = fr[64 + lane], B1 = fr[96 + lane];
        ull xv0[4] = { ((ull*)&A0)[0], ((ull*)&A0)[1], ((ull*)&B0)[0], ((ull*)&B0)[1] };
        ull xv1[4] = { ((ull*)&A1)[0], ((ull*)&A1)[1], ((ull*)&B1)[0], ((ull*)&B1)[1] };

        ull sp0, sq0 = 0ull, sp1, sq1 = 0ull;
        FMA2(sp0, xv0[0], ONE, xv0[1]);
        { ull tmp; FMA2(tmp, xv0[2], ONE, xv0[3]); FMA2(sp0, tmp, ONE, sp0); }
        FMA2(sp1, xv1[0], ONE, xv1[1]);
        { ull tmp; FMA2(tmp, xv1[2], ONE, xv1[3]); FMA2(sp1, tmp, ONE, sp1); }
        #pragma unroll
        for (int i = 0; i < 4; i++) { FMA2(sq0, xv0[i], xv0[i], sq0); FMA2(sq1, xv1[i], xv1[i], sq1); }
        float lo, hi, s10, s20, s11, s21;
        UNPK2(lo, hi, sp0); s10 = lo + hi;
        UNPK2(lo, hi, sq0); s20 = lo + hi;
        UNPK2(lo, hi, sp1); s11 = lo + hi;
        UNPK2(lo, hi, sq1); s21 = lo + hi;

        float p0[16], p1[16];
        #pragma unroll
        for (int s = 0; s < 16; s++) {
            ull t0 = 0ull, t1 = 0ull;
            #pragma unroll
            for (int i2 = 0; i2 < 4; i2++) {
                ull q = qk2[(s * 4 + i2) * 32 + lane];
                FMA2(t0, q, xv0[i2], t0);
                FMA2(t1, q, xv1[i2], t1);
            }
            UNPK2(lo, hi, t0); p0[s] = lo + hi;
            UNPK2(lo, hi, t1); p1[s] = lo + hi;
        }

        #pragma unroll
        for (int o = 16; o; o >>= 1) {
            s10 += __shfl_xor_sync(0xffffffffu, s10, o);
            s20 += __shfl_xor_sync(0xffffffffu, s20, o);
            s11 += __shfl_xor_sync(0xffffffffu, s11, o);
            s21 += __shfl_xor_sync(0xffffffffu, s21, o);
        }
        float m0 = s10 * (1.f / 256), m1 = s11 * (1.f / 256);
        float r0 = rsqrtf(s20 * (1.f / 256) - m0 * m0 + 1e-5f);
        float r1 = rsqrtf(s21 * (1.f / 256) - m1 * m1 + 1e-5f);

        float d0 = rs16(p0, lane);
        float d1 = rs16(p1, lane);
        float e0 = __expf(fmaf(d0, r0, fmaf(-r0 * m0, qs_l, c_l)));
        float e1 = __expf(fmaf(d1, r1, fmaf(-r1 * m1, qs_l, c_l)));
        float den0 = e0, den1 = e1;
        #pragma unroll
        for (int o = 16; o; o >>= 1) {
            den0 += __shfl_xor_sync(0xffffffffu, den0, o);
            den1 += __shfl_xor_sync(0xffffffffu, den1, o);
        }
        float a0 = e0 * __fdividef(2.0f, den0);
        float a1 = e1 * __fdividef(2.0f, den1);

        float outv = (lane & 1) ? a1 : a0;
        out_attn[(size_t)(2 * pi + (lane & 1)) * 16 + sl] = outv;
    }
}

// ================= launcher =================
extern "C" void kernel_launch(void* const* d_in, const int* in_sizes, int n_in,
                              void* d_out, int out_size) {
    const float* features   = (const float*)d_in[0];
    const float* ln_f_g     = (const float*)d_in[1];
    const float* ln_f_b     = (const float*)d_in[2];
    const float* ln_s_g     = (const float*)d_in[3];
    const float* ln_s_b     = (const float*)d_in[4];
    const float* ln_m_g     = (const float*)d_in[5];
    const float* ln_m_b     = (const float*)d_in[6];
    const float* Wq         = (const float*)d_in[7];
    const float* Wk         = (const float*)d_in[8];
    const float* Wv         = (const float*)d_in[9];
    const float* gru_wih    = (const float*)d_in[10];
    const float* gru_whh    = (const float*)d_in[11];
    const float* gru_bih    = (const float*)d_in[12];
    const float* gru_bhh    = (const float*)d_in[13];
    const float* mlp_w1     = (const float*)d_in[14];
    const float* mlp_b1     = (const float*)d_in[15];
    const float* mlp_w2     = (const float*)d_in[16];
    const float* mlp_b2     = (const float*)d_in[17];
    const float* slots_init = (const float*)d_in[18];
    // d_in[19] = num_iter (fixed at 2 -> exactly one update iteration)

    float* out = (float*)d_out;   // [0:4096) slots, [4096:) attn [N,16]

    const int DYN_A = 5 * 2048 * sizeof(ull);  // 80KB
    cudaFuncSetAttribute(k_pass_a, cudaFuncAttributeMaxDynamicSharedMemorySize, DYN_A);

    // warm L2 for the prep chain (Wq, Wk, slots_init)
    k_pref<<<64, 256>>>((const float4*)Wq, 16384, (const float4*)Wk, 16384,
                        (const float4*)slots_init, 1024,
                        (const float4*)0, 0, (const float4*)0, 0,
                        (const float4*)0, 0, (const float4*)0, 0);
    k_prep<<<KSLOT, 256>>>(slots_init, ln_s_g, ln_s_b, Wq);
    k_qk<<<16, 256>>>(Wk, ln_f_g, ln_f_b);
    k_pass_a<<<NBLK_A, 256, DYN_A>>>(features);
    // pass A streamed 128MB through L2 -> re-warm all mid-chain weights now
    k_pref<<<148, 256>>>((const float4*)Wv, 16384,
                         (const float4*)gru_wih, 49152, (const float4*)gru_whh, 49152,
                         (const float4*)mlp_w1, 32768, (const float4*)mlp_w2, 32768,
                         (const float4*)Wq, 16384, (const float4*)Wk, 16384);
    k_upd<<<KSLOT, 256>>>(Wv, ln_f_g, ln_f_b);
    k_gates<<<96, 256>>>(gru_wih, gru_whh, slots_init);
    k_tail<<<KSLOT, 512>>>(slots_init, gru_bih, gru_bhh, ln_m_g, ln_m_b,
                           mlp_w1, mlp_b1, mlp_w2, mlp_b2,
                           ln_s_g, ln_s_b, Wq, out);
    k_qk<<<16, 256>>>(Wk, ln_f_g, ln_f_b);
    k_pass_d<<<592, 256>>>(features, out + KSLOT * 256);
}